// round 12
// baseline (speedup 1.0000x reference)
#include <cuda_runtime.h>
#include <cuda_fp16.h>
#include <cstdint>

#define N_NODES 25000
#define N_PAD   25088          // 98 * 256
#define E_EDGES 400000
#define F_IN_   133
#define HC_     512
#define KP      144            // padded K (multiple of 16)
#define TPAD    152            // SMEM row stride in halves
#define BN_EPS_ 1e-5f
#define NEG_SLOPE_ 0.2f
#define W_SCALE 64.0f
#define W_INV   0.015625f
#define NROWT   98             // row tiles of 256 rows
#define NROWG   18             // persistent row groups
#define NCOLB   8              // column blocks

// ---------------- device scratch (static) -----------------------------------
__device__ __half g_xlh[(size_t)N_NODES * HC_];   // x@Wl in fp16
__device__ float  g_xr[(size_t)N_NODES * HC_];    // x@Wr fp32
__device__ __half g_xh [(size_t)N_PAD * KP];      // x in fp16
__device__ __half g_wh [(size_t)1024 * KP];       // W (scaled) in fp16
__device__ int    g_counts[N_NODES];
__device__ int    g_offsets[N_NODES + 1];
__device__ int    g_cursor[N_NODES];
__device__ int    g_csr_src[E_EDGES];
__device__ float2 g_gd[N_NODES];                  // {gout, dinv}

// ---------------- static streams/events -------------------------------------
static cudaStream_t g_s1;
static cudaEvent_t  g_eFork, g_eJoin, g_eW;
namespace {
struct StreamInit {
    StreamInit() {
        cudaStreamCreateWithFlags(&g_s1, cudaStreamNonBlocking);
        cudaEventCreateWithFlags(&g_eFork, cudaEventDisableTiming);
        cudaEventCreateWithFlags(&g_eJoin, cudaEventDisableTiming);
        cudaEventCreateWithFlags(&g_eW, cudaEventDisableTiming);
    }
} g_stream_init;
}

// ---------------- helpers ---------------------------------------------------
__device__ __forceinline__ uint32_t smem_to_u32(const void* p) {
    uint32_t a;
    asm("{ .reg .u64 t; cvta.to.shared.u64 t, %1; cvt.u32.u64 %0, t; }"
        : "=r"(a) : "l"(p));
    return a;
}
__device__ __forceinline__ void cp16(uint32_t dst, const void* src) {
    asm volatile("cp.async.cg.shared.global [%0], [%1], 16;" :: "r"(dst), "l"(src));
}

#define LDM_X4(r, addr) \
    asm volatile("ldmatrix.sync.aligned.m8n8.x4.shared.b16 {%0,%1,%2,%3}, [%4];" \
        : "=r"((r)[0]), "=r"((r)[1]), "=r"((r)[2]), "=r"((r)[3]) : "r"(addr))

__device__ __forceinline__ void mma16816(float* d, const uint32_t* a,
                                         uint32_t b0, uint32_t b1) {
    asm volatile("mma.sync.aligned.m16n8k16.row.col.f32.f16.f16.f32 "
        "{%0,%1,%2,%3}, {%4,%5,%6,%7}, {%8,%9}, {%0,%1,%2,%3};"
        : "+f"(d[0]), "+f"(d[1]), "+f"(d[2]), "+f"(d[3])
        : "r"(a[0]), "r"(a[1]), "r"(a[2]), "r"(a[3]), "r"(b0), "r"(b1));
}

// ---------------- conversions ------------------------------------------------
__global__ void conv_x_kernel(const float* __restrict__ x) {
    int i8 = blockIdx.x * blockDim.x + threadIdx.x;
    if (i8 >= N_PAD * KP / 8) return;
    int i = i8 * 8;
    int r = i / KP, k0 = i - r * KP;
    __half h[8];
    const float* xp = x + (size_t)r * F_IN_ + k0;
    #pragma unroll
    for (int j = 0; j < 8; j++) {
        int k = k0 + j;
        float v = (r < N_NODES && k < F_IN_) ? __ldg(xp + j) : 0.f;
        h[j] = __float2half_rn(v);
    }
    *(uint4*)(g_xh + i) = *(uint4*)h;
}

__global__ void conv_w_kernel(const float* __restrict__ Wl,
                              const float* __restrict__ Wr) {
    int i = blockIdx.x * blockDim.x + threadIdx.x;
    if (i >= 1024 * KP) return;
    int n = i / KP, k = i - n * KP;
    float v = 0.f;
    if (k < F_IN_)
        v = W_SCALE * ((n < HC_) ? Wl[(size_t)k * HC_ + n]
                                 : Wr[(size_t)k * HC_ + (n - HC_)]);
    g_wh[i] = __float2half_rn(v);
}

// ---------------- persistent fp16 mma GEMM, 512 thr, M=256 tiles -------------
#define A_TILE_H (256 * TPAD)
#define B_TILE_H (128 * TPAD)
#define SM_TOTAL ((2 * A_TILE_H + B_TILE_H) * 2)   // 194560 B

__global__ __launch_bounds__(512, 1) void gemm_mma_kernel() {
    extern __shared__ __half smem[];
    __half* A0 = smem;
    __half* A1 = A0 + A_TILE_H;
    __half* Bh = A1 + A_TILE_H;

    const int tid  = threadIdx.x;
    const int colb = blockIdx.x & 7;
    const int rowg = blockIdx.x >> 3;

    // pin B slab once (128 rows x 18 chunks)
    {
        const size_t brow0 = (size_t)colb * 128 * KP;
        for (int idx = tid; idx < 2304; idx += 512) {
            int row = idx / 18;
            int j   = idx - row * 18;
            *(uint4*)(Bh + row * TPAD + j * 8) =
                *(const uint4*)(g_wh + brow0 + (size_t)row * KP + j * 8);
        }
    }

    const uint32_t abase[2] = { smem_to_u32(A0), smem_to_u32(A1) };
    const uint32_t b_base = smem_to_u32(Bh);

    int c_row[9], c_col[9];
    #pragma unroll
    for (int j = 0; j < 9; j++) {
        int idx = tid + 512 * j;
        c_row[j] = idx / 18;
        c_col[j] = idx - c_row[j] * 18;
    }

    // prologue
    {
        const size_t arow0 = (size_t)rowg * 256 * KP;
        #pragma unroll
        for (int j = 0; j < 9; j++)
            cp16(abase[0] + (uint32_t)(c_row[j] * TPAD + c_col[j] * 8) * 2,
                 g_xh + arow0 + (size_t)c_row[j] * KP + c_col[j] * 8);
        asm volatile("cp.async.commit_group;");
    }

    const int wid = tid >> 5;
    const int lid = tid & 31;
    const int wm = (wid & 7) * 32;
    const int wn = (wid >> 3) * 64;

    const uint32_t a_off0 = ((uint32_t)(wm + (lid & 15)) * TPAD + (lid >> 4) * 8) * 2;
    const uint32_t b_row  = wn + (lid & 7) + ((lid >> 4) << 3);
    const uint32_t b_off0 = ((uint32_t)b_row * TPAD + ((lid >> 3) & 1) * 8) * 2;

    const int gc0 = colb * 128;
    const bool is_xl = (gc0 < HC_);
    const int ocol0 = is_xl ? gc0 : gc0 - HC_;

    int buf = 0;
    for (int rt = rowg; rt < NROWT; rt += NROWG) {
        const int nrt = rt + NROWG;
        if (nrt < NROWT) {
            const size_t arow0 = (size_t)nrt * 256 * KP;
            #pragma unroll
            for (int j = 0; j < 9; j++)
                cp16(abase[buf ^ 1] + (uint32_t)(c_row[j] * TPAD + c_col[j] * 8) * 2,
                     g_xh + arow0 + (size_t)c_row[j] * KP + c_col[j] * 8);
            asm volatile("cp.async.commit_group;");
            asm volatile("cp.async.wait_group 1;");
        } else {
            asm volatile("cp.async.wait_group 0;");
        }
        __syncthreads();

        const uint32_t a_base = abase[buf];

        float acc[2][8][4];
        #pragma unroll
        for (int mt = 0; mt < 2; mt++)
            #pragma unroll
            for (int nt = 0; nt < 8; nt++)
                #pragma unroll
                for (int j = 0; j < 4; j++) acc[mt][nt][j] = 0.f;

        #pragma unroll
        for (int ks = 0; ks < 9; ks++) {
            const uint32_t kb = ks * 32;
            uint32_t a_hi[2][4];
            #pragma unroll
            for (int mt = 0; mt < 2; mt++)
                LDM_X4(a_hi[mt], a_base + a_off0 + mt * (16 * TPAD * 2) + kb);
            uint32_t b_hi[4][4];
            #pragma unroll
            for (int np = 0; np < 4; np++)
                LDM_X4(b_hi[np], b_base + b_off0 + np * (16 * TPAD * 2) + kb);
            #pragma unroll
            for (int mt = 0; mt < 2; mt++) {
                #pragma unroll
                for (int nt = 0; nt < 8; nt++) {
                    const uint32_t* bh = &b_hi[nt >> 1][(nt & 1) * 2];
                    mma16816(acc[mt][nt], a_hi[mt], bh[0], bh[1]);
                }
            }
        }

        #pragma unroll
        for (int mt = 0; mt < 2; mt++) {
            int r0 = rt * 256 + wm + mt * 16 + (lid >> 2);
            #pragma unroll
            for (int nt = 0; nt < 8; nt++) {
                int col = ocol0 + wn + nt * 8 + (lid & 3) * 2;
                float v0 = acc[mt][nt][0] * W_INV, v1 = acc[mt][nt][1] * W_INV;
                float v2 = acc[mt][nt][2] * W_INV, v3 = acc[mt][nt][3] * W_INV;
                if (is_xl) {
                    if (r0 < N_NODES)
                        *(__half2*)(g_xlh + (size_t)r0 * HC_ + col) = __floats2half2_rn(v0, v1);
                    if (r0 + 8 < N_NODES)
                        *(__half2*)(g_xlh + (size_t)(r0 + 8) * HC_ + col) = __floats2half2_rn(v2, v3);
                } else {
                    if (r0 < N_NODES)
                        *(float2*)(g_xr + (size_t)r0 * HC_ + col) = make_float2(v0, v1);
                    if (r0 + 8 < N_NODES)
                        *(float2*)(g_xr + (size_t)(r0 + 8) * HC_ + col) = make_float2(v2, v3);
                }
            }
        }
        __syncthreads();
        buf ^= 1;
    }
}

// ---------------- CSR build -------------------------------------------------
__global__ void hist_kernel(const int* __restrict__ ei) {
    int e = blockIdx.x * blockDim.x + threadIdx.x;
    if (e < E_EDGES) atomicAdd(&g_counts[ei[E_EDGES + e]], 1);
}

__global__ __launch_bounds__(1024) void scan_kernel() {
    __shared__ int warp_sums[32];
    __shared__ int s_carry;
    const int t = threadIdx.x;
    const int lane = t & 31;
    const int w = t >> 5;
    if (t == 0) { s_carry = 0; g_offsets[0] = 0; }
    __syncthreads();
    for (int base = 0; base < N_NODES; base += 1024) {
        int i = base + t;
        int v = (i < N_NODES) ? g_counts[i] : 0;
        int s = v;
        #pragma unroll
        for (int d = 1; d < 32; d <<= 1) {
            int n = __shfl_up_sync(0xffffffffu, s, d);
            if (lane >= d) s += n;
        }
        if (lane == 31) warp_sums[w] = s;
        __syncthreads();
        if (w == 0) {
            int ws = warp_sums[lane];
            #pragma unroll
            for (int d = 1; d < 32; d <<= 1) {
                int n = __shfl_up_sync(0xffffffffu, ws, d);
                if (lane >= d) ws += n;
            }
            warp_sums[lane] = ws;
        }
        __syncthreads();
        int incl = s + (w > 0 ? warp_sums[w - 1] : 0);
        int carry = s_carry;
        if (i < N_NODES) {
            g_offsets[i + 1] = carry + incl;
            g_cursor[i] = carry + incl - v;
        }
        __syncthreads();
        if (t == 1023) s_carry = carry + incl;
        __syncthreads();
    }
}

__global__ void scatter_kernel(const int* __restrict__ ei) {
    int e = blockIdx.x * blockDim.x + threadIdx.x;
    if (e < E_EDGES) {
        int d = ei[E_EDGES + e];
        int p = atomicAdd(&g_cursor[d], 1);
        g_csr_src[p] = ei[e];
    }
}

// ---------------- GATv2 aggregation: 2 warps/node, depth-2 edge pipeline -----
__global__ __launch_bounds__(256) void agg_kernel(
    const float* __restrict__ att,  const float* __restrict__ b1,
    const float* __restrict__ bn_g, const float* __restrict__ bn_b,
    const float* __restrict__ bn_m, const float* __restrict__ bn_v,
    const float* __restrict__ prelu_w, const float* __restrict__ Wg)
{
    const int gw   = threadIdx.x >> 5;            // warp in block (0..7)
    const int node = blockIdx.x * 4 + (gw >> 1);
    const int half = gw & 1;
    const int lane = threadIdx.x & 31;
    __shared__ float red[8];

    bool active = (node < N_NODES);
    int cnt = 1;
    float part = 0.f;

    const int c0 = half * 256 + lane * 8;
    const uint4* __restrict__ xlrow = (const uint4*)g_xlh;   // 64 uint4 per row
    const uint32_t roff = half * 32 + lane;
    const int* __restrict__ csr = g_csr_src;

    if (active) {
        float xr[8], at[8];
        {
            const float4* p = (const float4*)(g_xr + (size_t)node * HC_ + c0);
            const float4* q = (const float4*)(att + c0);
            #pragma unroll
            for (int i = 0; i < 2; i++) {
                float4 v = __ldg(p + i); xr[4*i]=v.x; xr[4*i+1]=v.y; xr[4*i+2]=v.z; xr[4*i+3]=v.w;
                float4 a = __ldg(q + i); at[4*i]=a.x; at[4*i+1]=a.y; at[4*i+2]=a.z; at[4*i+3]=a.w;
            }
        }
        const int rs = g_offsets[node];
        const int re = g_offsets[node + 1];
        cnt = re - rs + 1;

        float acc[8];
        #pragma unroll
        for (int i = 0; i < 8; i++) acc[i] = 0.f;
        float den = 0.f;

        // depth-2 pipeline: edge k data = row(csr[rs+k-1]), edge 0 = self.
        uint4 u  = __ldg(&xlrow[(size_t)node * 64 + roff]);            // d0
        int  idx2 = (cnt > 1) ? __ldg(csr + rs) : 0;                   // src of d1
        uint4 n  = (cnt > 1) ? __ldg(&xlrow[(size_t)idx2 * 64 + roff]) : u;  // d1
        int  idxN = (cnt > 2) ? __ldg(csr + rs + 1) : 0;               // src of d2

        for (int k = 0; k < cnt; k++) {
            // issue d_{k+2} with index fetched last iteration
            uint4 nn = (k + 2 < cnt) ? __ldg(&xlrow[(size_t)idxN * 64 + roff]) : n;
            int idxF = (k + 3 < cnt) ? __ldg(csr + rs + k + 2) : 0;

            float f[8];
            {
                float2 t;
                t = __half22float2(*(__half2*)&u.x); f[0]=t.x; f[1]=t.y;
                t = __half22float2(*(__half2*)&u.y); f[2]=t.x; f[3]=t.y;
                t = __half22float2(*(__half2*)&u.z); f[4]=t.x; f[5]=t.y;
                t = __half22float2(*(__half2*)&u.w); f[6]=t.x; f[7]=t.y;
            }
            float p2 = 0.f;
            #pragma unroll
            for (int i = 0; i < 8; i++) {
                float s = f[i] + xr[i];
                s = s > 0.f ? s : NEG_SLOPE_ * s;
                p2 += at[i] * s;
            }
            p2 += __shfl_xor_sync(0xffffffffu, p2, 1);
            p2 += __shfl_xor_sync(0xffffffffu, p2, 2);
            p2 += __shfl_xor_sync(0xffffffffu, p2, 4);  // per-head score (8 lanes)
            float w = __expf(p2);
            den += w;
            #pragma unroll
            for (int i = 0; i < 8; i++) acc[i] += w * f[i];

            u = n; n = nn; idxN = idxF;
        }

        const float inv = 1.f / den;
        const float pw = prelu_w[0];
        #pragma unroll
        for (int i = 0; i < 2; i++) {
            float4 bb = __ldg((const float4*)(b1   + c0) + i);
            float4 gm = __ldg((const float4*)(bn_g + c0) + i);
            float4 bt = __ldg((const float4*)(bn_b + c0) + i);
            float4 mv = __ldg((const float4*)(bn_m + c0) + i);
            float4 vv = __ldg((const float4*)(bn_v + c0) + i);
            float4 wg = __ldg((const float4*)(Wg   + c0) + i);
            float h;
            h = acc[4*i+0] * inv + bb.x;
            h = (h - mv.x) * rsqrtf(vv.x + BN_EPS_) * gm.x + bt.x;
            h = h >= 0.f ? h : pw * h;  part += h * wg.x;
            h = acc[4*i+1] * inv + bb.y;
            h = (h - mv.y) * rsqrtf(vv.y + BN_EPS_) * gm.y + bt.y;
            h = h >= 0.f ? h : pw * h;  part += h * wg.y;
            h = acc[4*i+2] * inv + bb.z;
            h = (h - mv.z) * rsqrtf(vv.z + BN_EPS_) * gm.z + bt.z;
            h = h >= 0.f ? h : pw * h;  part += h * wg.z;
            h = acc[4*i+3] * inv + bb.w;
            h = (h - mv.w) * rsqrtf(vv.w + BN_EPS_) * gm.w + bt.w;
            h = h >= 0.f ? h : pw * h;  part += h * wg.w;
        }
        #pragma unroll
        for (int o = 16; o; o >>= 1) part += __shfl_xor_sync(0xffffffffu, part, o);
    }
    if (lane == 0) red[gw] = part;
    __syncthreads();
    if (active && half == 0 && lane == 0)
        g_gd[node] = make_float2(red[gw] + red[gw + 1], rsqrtf((float)cnt));
}

// ---------------- GCNConv (OUT=1): 8 lanes per node --------------------------
__global__ void gcn_kernel(const float* __restrict__ bg, float* __restrict__ out) {
    int gthread = blockIdx.x * blockDim.x + threadIdx.x;
    int node = gthread >> 3;
    int sl   = gthread & 7;
    if (node >= N_NODES) return;
    int rs = g_offsets[node], re = g_offsets[node + 1];
    float2 self = g_gd[node];
    float di = self.y;
    float s = (sl == 0) ? di * self.x : 0.f;
    for (int j = rs + sl; j < re; j += 8) {
        float2 gd = __ldg(&g_gd[g_csr_src[j]]);
        s += gd.y * gd.x;
    }
    s += __shfl_xor_sync(0xffffffffu, s, 1);
    s += __shfl_xor_sync(0xffffffffu, s, 2);
    s += __shfl_xor_sync(0xffffffffu, s, 4);
    if (sl == 0) out[node] = bg[0] + di * s;
}

// ---------------- launch ----------------------------------------------------
extern "C" void kernel_launch(void* const* d_in, const int* in_sizes, int n_in,
                              void* d_out, int out_size)
{
    const float* x    = (const float*)d_in[0];
    const int*   ei   = (const int*)  d_in[1];
    const float* Wl   = (const float*)d_in[2];
    const float* Wr   = (const float*)d_in[3];
    const float* att  = (const float*)d_in[4];
    const float* b1   = (const float*)d_in[5];
    const float* bn_g = (const float*)d_in[6];
    const float* bn_b = (const float*)d_in[7];
    const float* bn_m = (const float*)d_in[8];
    const float* bn_v = (const float*)d_in[9];
    const float* pw   = (const float*)d_in[10];
    const float* Wg   = (const float*)d_in[11];
    const float* bg   = (const float*)d_in[12];
    float* out = (float*)d_out;

    cudaFuncSetAttribute(gemm_mma_kernel,
                         cudaFuncAttributeMaxDynamicSharedMemorySize, SM_TOTAL);

    void* countsPtr = nullptr;
    cudaGetSymbolAddress(&countsPtr, g_counts);

    // Fork: conv_w then CSR chain on side stream.
    cudaEventRecord(g_eFork, 0);
    cudaStreamWaitEvent(g_s1, g_eFork, 0);
    conv_w_kernel<<<(1024 * KP + 255) / 256, 256, 0, g_s1>>>(Wl, Wr);
    cudaEventRecord(g_eW, g_s1);
    cudaMemsetAsync(countsPtr, 0, N_NODES * sizeof(int), g_s1);
    hist_kernel<<<(E_EDGES + 255) / 256, 256, 0, g_s1>>>(ei);
    scan_kernel<<<1, 1024, 0, g_s1>>>();
    scatter_kernel<<<(E_EDGES + 255) / 256, 256, 0, g_s1>>>(ei);
    cudaEventRecord(g_eJoin, g_s1);

    // Main stream: conv_x, wait for conv_w, then persistent GEMM.
    conv_x_kernel<<<(N_PAD * KP / 8 + 255) / 256, 256>>>(x);
    cudaStreamWaitEvent(0, g_eW, 0);
    gemm_mma_kernel<<<NROWG * NCOLB, 512, SM_TOTAL>>>();

    // Join, then aggregation + GCN.
    cudaStreamWaitEvent(0, g_eJoin, 0);
    agg_kernel<<<(N_NODES + 3) / 4, 256>>>(att, b1, bn_g, bn_b, bn_m, bn_v, pw, Wg);
    gcn_kernel<<<(N_NODES * 8 + 255) / 256, 256>>>(bg, out);
}

// round 13
// speedup vs baseline: 1.0321x; 1.0321x over previous
#include <cuda_runtime.h>
#include <cuda_fp16.h>
#include <cstdint>

#define N_NODES 25000
#define N_PAD   25088          // 98 * 256
#define E_EDGES 400000
#define F_IN_   133
#define HC_     512
#define KP      144            // padded K (multiple of 16)
#define TPAD    152            // SMEM row stride in halves
#define BN_EPS_ 1e-5f
#define NEG_SLOPE_ 0.2f
#define W_SCALE 64.0f
#define W_INV   0.015625f
#define NROWT   98             // row tiles of 256 rows
#define NROWG   18             // persistent row groups
#define NCOLB   8              // column blocks

// ---------------- device scratch (static) -----------------------------------
__device__ __half g_xlh[(size_t)N_NODES * HC_];   // x@Wl in fp16
__device__ __half g_xrh[(size_t)N_NODES * HC_];   // x@Wr in fp16
__device__ __half g_xh [(size_t)N_PAD * KP];      // x in fp16
__device__ __half g_wh [(size_t)1024 * KP];       // W (scaled) in fp16
__device__ int    g_counts[N_NODES];
__device__ int    g_offsets[N_NODES + 1];
__device__ int    g_cursor[N_NODES];
__device__ int    g_csr_src[E_EDGES];
__device__ float2 g_gd[N_NODES];                  // {gout, dinv}

// ---------------- static streams/events -------------------------------------
static cudaStream_t g_s1;
static cudaEvent_t  g_eFork, g_eJoin, g_eW;
namespace {
struct StreamInit {
    StreamInit() {
        cudaStreamCreateWithFlags(&g_s1, cudaStreamNonBlocking);
        cudaEventCreateWithFlags(&g_eFork, cudaEventDisableTiming);
        cudaEventCreateWithFlags(&g_eJoin, cudaEventDisableTiming);
        cudaEventCreateWithFlags(&g_eW, cudaEventDisableTiming);
    }
} g_stream_init;
}

// ---------------- helpers ---------------------------------------------------
__device__ __forceinline__ uint32_t smem_to_u32(const void* p) {
    uint32_t a;
    asm("{ .reg .u64 t; cvta.to.shared.u64 t, %1; cvt.u32.u64 %0, t; }"
        : "=r"(a) : "l"(p));
    return a;
}
__device__ __forceinline__ void cp16(uint32_t dst, const void* src) {
    asm volatile("cp.async.cg.shared.global [%0], [%1], 16;" :: "r"(dst), "l"(src));
}

#define LDM_X4(r, addr) \
    asm volatile("ldmatrix.sync.aligned.m8n8.x4.shared.b16 {%0,%1,%2,%3}, [%4];" \
        : "=r"((r)[0]), "=r"((r)[1]), "=r"((r)[2]), "=r"((r)[3]) : "r"(addr))

__device__ __forceinline__ void mma16816(float* d, const uint32_t* a,
                                         uint32_t b0, uint32_t b1) {
    asm volatile("mma.sync.aligned.m16n8k16.row.col.f32.f16.f16.f32 "
        "{%0,%1,%2,%3}, {%4,%5,%6,%7}, {%8,%9}, {%0,%1,%2,%3};"
        : "+f"(d[0]), "+f"(d[1]), "+f"(d[2]), "+f"(d[3])
        : "r"(a[0]), "r"(a[1]), "r"(a[2]), "r"(a[3]), "r"(b0), "r"(b1));
}

// ---------------- conversions ------------------------------------------------
__global__ void conv_x_kernel(const float* __restrict__ x) {
    int i8 = blockIdx.x * blockDim.x + threadIdx.x;
    if (i8 >= N_PAD * KP / 8) return;
    int i = i8 * 8;
    int r = i / KP, k0 = i - r * KP;
    __half h[8];
    const float* xp = x + (size_t)r * F_IN_ + k0;
    #pragma unroll
    for (int j = 0; j < 8; j++) {
        int k = k0 + j;
        float v = (r < N_NODES && k < F_IN_) ? __ldg(xp + j) : 0.f;
        h[j] = __float2half_rn(v);
    }
    *(uint4*)(g_xh + i) = *(uint4*)h;
}

__global__ void conv_w_kernel(const float* __restrict__ Wl,
                              const float* __restrict__ Wr) {
    int i = blockIdx.x * blockDim.x + threadIdx.x;
    if (i >= 1024 * KP) return;
    int n = i / KP, k = i - n * KP;
    float v = 0.f;
    if (k < F_IN_)
        v = W_SCALE * ((n < HC_) ? Wl[(size_t)k * HC_ + n]
                                 : Wr[(size_t)k * HC_ + (n - HC_)]);
    g_wh[i] = __float2half_rn(v);
}

// ---------------- persistent fp16 mma GEMM, 512 thr, M=256 tiles -------------
#define A_TILE_H (256 * TPAD)
#define B_TILE_H (128 * TPAD)
#define SM_TOTAL ((2 * A_TILE_H + B_TILE_H) * 2)   // 194560 B

__global__ __launch_bounds__(512, 1) void gemm_mma_kernel() {
    extern __shared__ __half smem[];
    __half* A0 = smem;
    __half* A1 = A0 + A_TILE_H;
    __half* Bh = A1 + A_TILE_H;

    const int tid  = threadIdx.x;
    const int colb = blockIdx.x & 7;
    const int rowg = blockIdx.x >> 3;

    // pin B slab once (128 rows x 18 chunks)
    {
        const size_t brow0 = (size_t)colb * 128 * KP;
        for (int idx = tid; idx < 2304; idx += 512) {
            int row = idx / 18;
            int j   = idx - row * 18;
            *(uint4*)(Bh + row * TPAD + j * 8) =
                *(const uint4*)(g_wh + brow0 + (size_t)row * KP + j * 8);
        }
    }

    const uint32_t abase[2] = { smem_to_u32(A0), smem_to_u32(A1) };
    const uint32_t b_base = smem_to_u32(Bh);

    int c_row[9], c_col[9];
    #pragma unroll
    for (int j = 0; j < 9; j++) {
        int idx = tid + 512 * j;
        c_row[j] = idx / 18;
        c_col[j] = idx - c_row[j] * 18;
    }

    // prologue
    {
        const size_t arow0 = (size_t)rowg * 256 * KP;
        #pragma unroll
        for (int j = 0; j < 9; j++)
            cp16(abase[0] + (uint32_t)(c_row[j] * TPAD + c_col[j] * 8) * 2,
                 g_xh + arow0 + (size_t)c_row[j] * KP + c_col[j] * 8);
        asm volatile("cp.async.commit_group;");
    }

    const int wid = tid >> 5;
    const int lid = tid & 31;
    const int wm = (wid & 7) * 32;
    const int wn = (wid >> 3) * 64;

    const uint32_t a_off0 = ((uint32_t)(wm + (lid & 15)) * TPAD + (lid >> 4) * 8) * 2;
    const uint32_t b_row  = wn + (lid & 7) + ((lid >> 4) << 3);
    const uint32_t b_off0 = ((uint32_t)b_row * TPAD + ((lid >> 3) & 1) * 8) * 2;

    const int gc0 = colb * 128;
    __half* obase = (gc0 < HC_) ? g_xlh : g_xrh;
    const int ocol0 = (gc0 < HC_) ? gc0 : gc0 - HC_;

    int buf = 0;
    for (int rt = rowg; rt < NROWT; rt += NROWG) {
        const int nrt = rt + NROWG;
        if (nrt < NROWT) {
            const size_t arow0 = (size_t)nrt * 256 * KP;
            #pragma unroll
            for (int j = 0; j < 9; j++)
                cp16(abase[buf ^ 1] + (uint32_t)(c_row[j] * TPAD + c_col[j] * 8) * 2,
                     g_xh + arow0 + (size_t)c_row[j] * KP + c_col[j] * 8);
            asm volatile("cp.async.commit_group;");
            asm volatile("cp.async.wait_group 1;");
        } else {
            asm volatile("cp.async.wait_group 0;");
        }
        __syncthreads();

        const uint32_t a_base = abase[buf];

        float acc[2][8][4];
        #pragma unroll
        for (int mt = 0; mt < 2; mt++)
            #pragma unroll
            for (int nt = 0; nt < 8; nt++)
                #pragma unroll
                for (int j = 0; j < 4; j++) acc[mt][nt][j] = 0.f;

        #pragma unroll
        for (int ks = 0; ks < 9; ks++) {
            const uint32_t kb = ks * 32;
            uint32_t a_hi[2][4];
            #pragma unroll
            for (int mt = 0; mt < 2; mt++)
                LDM_X4(a_hi[mt], a_base + a_off0 + mt * (16 * TPAD * 2) + kb);
            uint32_t b_hi[4][4];
            #pragma unroll
            for (int np = 0; np < 4; np++)
                LDM_X4(b_hi[np], b_base + b_off0 + np * (16 * TPAD * 2) + kb);
            #pragma unroll
            for (int mt = 0; mt < 2; mt++) {
                #pragma unroll
                for (int nt = 0; nt < 8; nt++) {
                    const uint32_t* bh = &b_hi[nt >> 1][(nt & 1) * 2];
                    mma16816(acc[mt][nt], a_hi[mt], bh[0], bh[1]);
                }
            }
        }

        #pragma unroll
        for (int mt = 0; mt < 2; mt++) {
            int r0 = rt * 256 + wm + mt * 16 + (lid >> 2);
            #pragma unroll
            for (int nt = 0; nt < 8; nt++) {
                int col = ocol0 + wn + nt * 8 + (lid & 3) * 2;
                float v0 = acc[mt][nt][0] * W_INV, v1 = acc[mt][nt][1] * W_INV;
                float v2 = acc[mt][nt][2] * W_INV, v3 = acc[mt][nt][3] * W_INV;
                if (r0 < N_NODES)
                    *(__half2*)(obase + (size_t)r0 * HC_ + col) = __floats2half2_rn(v0, v1);
                if (r0 + 8 < N_NODES)
                    *(__half2*)(obase + (size_t)(r0 + 8) * HC_ + col) = __floats2half2_rn(v2, v3);
            }
        }
        __syncthreads();
        buf ^= 1;
    }
}

// ---------------- CSR build -------------------------------------------------
__global__ void hist_kernel(const int* __restrict__ ei) {
    int e = blockIdx.x * blockDim.x + threadIdx.x;
    if (e < E_EDGES) atomicAdd(&g_counts[ei[E_EDGES + e]], 1);
}

__global__ __launch_bounds__(1024) void scan_kernel() {
    __shared__ int warp_sums[32];
    __shared__ int s_carry;
    const int t = threadIdx.x;
    const int lane = t & 31;
    const int w = t >> 5;
    if (t == 0) { s_carry = 0; g_offsets[0] = 0; }
    __syncthreads();
    for (int base = 0; base < N_NODES; base += 1024) {
        int i = base + t;
        int v = (i < N_NODES) ? g_counts[i] : 0;
        int s = v;
        #pragma unroll
        for (int d = 1; d < 32; d <<= 1) {
            int n = __shfl_up_sync(0xffffffffu, s, d);
            if (lane >= d) s += n;
        }
        if (lane == 31) warp_sums[w] = s;
        __syncthreads();
        if (w == 0) {
            int ws = warp_sums[lane];
            #pragma unroll
            for (int d = 1; d < 32; d <<= 1) {
                int n = __shfl_up_sync(0xffffffffu, ws, d);
                if (lane >= d) ws += n;
            }
            warp_sums[lane] = ws;
        }
        __syncthreads();
        int incl = s + (w > 0 ? warp_sums[w - 1] : 0);
        int carry = s_carry;
        if (i < N_NODES) {
            g_offsets[i + 1] = carry + incl;
            g_cursor[i] = carry + incl - v;
        }
        __syncthreads();
        if (t == 1023) s_carry = carry + incl;
        __syncthreads();
    }
}

__global__ void scatter_kernel(const int* __restrict__ ei) {
    int e = blockIdx.x * blockDim.x + threadIdx.x;
    if (e < E_EDGES) {
        int d = ei[E_EDGES + e];
        int p = atomicAdd(&g_cursor[d], 1);
        g_csr_src[p] = ei[e];
    }
}

// ---------------- GATv2 aggregation: 2 warps per node, 8 ch per lane ---------
// (round-11 structure; xr now fp16)
__global__ __launch_bounds__(256) void agg_kernel(
    const float* __restrict__ att,  const float* __restrict__ b1,
    const float* __restrict__ bn_g, const float* __restrict__ bn_b,
    const float* __restrict__ bn_m, const float* __restrict__ bn_v,
    const float* __restrict__ prelu_w, const float* __restrict__ Wg)
{
    const int gw   = threadIdx.x >> 5;            // warp in block (0..7)
    const int node = blockIdx.x * 4 + (gw >> 1);
    const int half = gw & 1;
    const int lane = threadIdx.x & 31;
    __shared__ float red[8];

    bool active = (node < N_NODES);
    int rs = 0, re = 0, cnt = 1;
    float xr[8], at[8];
    float acc[8];
    float den = 0.f;

    const int c0 = half * 256 + lane * 8;
    const uint4* __restrict__ xlrow = (const uint4*)g_xlh;   // 64 uint4 per row
    const uint4* __restrict__ xrrow = (const uint4*)g_xrh;
    const size_t uidx = (size_t)node * 64 + half * 32 + lane;

    if (active) {
        {
            uint4 xv = __ldg(&xrrow[uidx]);
            float2 t;
            t = __half22float2(*(__half2*)&xv.x); xr[0]=t.x; xr[1]=t.y;
            t = __half22float2(*(__half2*)&xv.y); xr[2]=t.x; xr[3]=t.y;
            t = __half22float2(*(__half2*)&xv.z); xr[4]=t.x; xr[5]=t.y;
            t = __half22float2(*(__half2*)&xv.w); xr[6]=t.x; xr[7]=t.y;
        }
        {
            const float4* q = (const float4*)(att + c0);
            #pragma unroll
            for (int i = 0; i < 2; i++) {
                float4 a = __ldg(q + i);
                at[4*i]=a.x; at[4*i+1]=a.y; at[4*i+2]=a.z; at[4*i+3]=a.w;
            }
        }
        rs = g_offsets[node];
        re = g_offsets[node + 1];
        cnt = re - rs + 1;
        #pragma unroll
        for (int i = 0; i < 8; i++) acc[i] = 0.f;

        uint4 u = __ldg(&xlrow[uidx]);      // self loop first
        for (int k = 0; k < cnt; k++) {
            uint4 n = u;
            if (k + 1 < cnt) {
                int ns = g_csr_src[rs + k];
                n = __ldg(&xlrow[(size_t)ns * 64 + half * 32 + lane]);
            }
            float f[8];
            {
                float2 t;
                t = __half22float2(*(__half2*)&u.x); f[0]=t.x; f[1]=t.y;
                t = __half22float2(*(__half2*)&u.y); f[2]=t.x; f[3]=t.y;
                t = __half22float2(*(__half2*)&u.z); f[4]=t.x; f[5]=t.y;
                t = __half22float2(*(__half2*)&u.w); f[6]=t.x; f[7]=t.y;
            }
            float p2 = 0.f;
            #pragma unroll
            for (int i = 0; i < 8; i++) {
                float s = f[i] + xr[i];
                s = s > 0.f ? s : NEG_SLOPE_ * s;
                p2 += at[i] * s;
            }
            p2 += __shfl_xor_sync(0xffffffffu, p2, 1);
            p2 += __shfl_xor_sync(0xffffffffu, p2, 2);
            p2 += __shfl_xor_sync(0xffffffffu, p2, 4);  // per-head score (8 lanes)
            float w = __expf(p2);
            den += w;
            #pragma unroll
            for (int i = 0; i < 8; i++) acc[i] += w * f[i];
            u = n;
        }
    }

    float part = 0.f;
    if (active) {
        const float inv = 1.f / den;
        const float pw = prelu_w[0];
        #pragma unroll
        for (int i = 0; i < 2; i++) {
            float4 bb = __ldg((const float4*)(b1   + c0) + i);
            float4 gm = __ldg((const float4*)(bn_g + c0) + i);
            float4 bt = __ldg((const float4*)(bn_b + c0) + i);
            float4 mv = __ldg((const float4*)(bn_m + c0) + i);
            float4 vv = __ldg((const float4*)(bn_v + c0) + i);
            float4 wg = __ldg((const float4*)(Wg   + c0) + i);
            float h;
            h = acc[4*i+0] * inv + bb.x;
            h = (h - mv.x) * rsqrtf(vv.x + BN_EPS_) * gm.x + bt.x;
            h = h >= 0.f ? h : pw * h;  part += h * wg.x;
            h = acc[4*i+1] * inv + bb.y;
            h = (h - mv.y) * rsqrtf(vv.y + BN_EPS_) * gm.y + bt.y;
            h = h >= 0.f ? h : pw * h;  part += h * wg.y;
            h = acc[4*i+2] * inv + bb.z;
            h = (h - mv.z) * rsqrtf(vv.z + BN_EPS_) * gm.z + bt.z;
            h = h >= 0.f ? h : pw * h;  part += h * wg.z;
            h = acc[4*i+3] * inv + bb.w;
            h = (h - mv.w) * rsqrtf(vv.w + BN_EPS_) * gm.w + bt.w;
            h = h >= 0.f ? h : pw * h;  part += h * wg.w;
        }
        #pragma unroll
        for (int o = 16; o; o >>= 1) part += __shfl_xor_sync(0xffffffffu, part, o);
    }
    if (lane == 0) red[gw] = part;
    __syncthreads();
    if (active && half == 0 && lane == 0)
        g_gd[node] = make_float2(red[gw] + red[gw + 1], rsqrtf((float)cnt));
}

// ---------------- GCNConv (OUT=1): 8 lanes per node --------------------------
__global__ void gcn_kernel(const float* __restrict__ bg, float* __restrict__ out) {
    int gthread = blockIdx.x * blockDim.x + threadIdx.x;
    int node = gthread >> 3;
    int sl   = gthread & 7;
    if (node >= N_NODES) return;
    int rs = g_offsets[node], re = g_offsets[node + 1];
    float2 self = g_gd[node];
    float di = self.y;
    float s = (sl == 0) ? di * self.x : 0.f;
    for (int j = rs + sl; j < re; j += 8) {
        float2 gd = __ldg(&g_gd[g_csr_src[j]]);
        s += gd.y * gd.x;
    }
    s += __shfl_xor_sync(0xffffffffu, s, 1);
    s += __shfl_xor_sync(0xffffffffu, s, 2);
    s += __shfl_xor_sync(0xffffffffu, s, 4);
    if (sl == 0) out[node] = bg[0] + di * s;
}

// ---------------- launch ----------------------------------------------------
extern "C" void kernel_launch(void* const* d_in, const int* in_sizes, int n_in,
                              void* d_out, int out_size)
{
    const float* x    = (const float*)d_in[0];
    const int*   ei   = (const int*)  d_in[1];
    const float* Wl   = (const float*)d_in[2];
    const float* Wr   = (const float*)d_in[3];
    const float* att  = (const float*)d_in[4];
    const float* b1   = (const float*)d_in[5];
    const float* bn_g = (const float*)d_in[6];
    const float* bn_b = (const float*)d_in[7];
    const float* bn_m = (const float*)d_in[8];
    const float* bn_v = (const float*)d_in[9];
    const float* pw   = (const float*)d_in[10];
    const float* Wg   = (const float*)d_in[11];
    const float* bg   = (const float*)d_in[12];
    float* out = (float*)d_out;

    cudaFuncSetAttribute(gemm_mma_kernel,
                         cudaFuncAttributeMaxDynamicSharedMemorySize, SM_TOTAL);

    void* countsPtr = nullptr;
    cudaGetSymbolAddress(&countsPtr, g_counts);

    // Fork: conv_w then CSR chain on side stream.
    cudaEventRecord(g_eFork, 0);
    cudaStreamWaitEvent(g_s1, g_eFork, 0);
    conv_w_kernel<<<(1024 * KP + 255) / 256, 256, 0, g_s1>>>(Wl, Wr);
    cudaEventRecord(g_eW, g_s1);
    cudaMemsetAsync(countsPtr, 0, N_NODES * sizeof(int), g_s1);
    hist_kernel<<<(E_EDGES + 255) / 256, 256, 0, g_s1>>>(ei);
    scan_kernel<<<1, 1024, 0, g_s1>>>();
    scatter_kernel<<<(E_EDGES + 255) / 256, 256, 0, g_s1>>>(ei);
    cudaEventRecord(g_eJoin, g_s1);

    // Main stream: conv_x, wait for conv_w, then persistent GEMM.
    conv_x_kernel<<<(N_PAD * KP / 8 + 255) / 256, 256>>>(x);
    cudaStreamWaitEvent(0, g_eW, 0);
    gemm_mma_kernel<<<NROWG * NCOLB, 512, SM_TOTAL>>>();

    // Join, then aggregation + GCN.
    cudaStreamWaitEvent(0, g_eJoin, 0);
    agg_kernel<<<(N_NODES + 3) / 4, 256>>>(att, b1, bn_g, bn_b, bn_m, bn_v, pw, Wg);
    gcn_kernel<<<(N_NODES * 8 + 255) / 256, 256>>>(bg, out);
}

// round 14
// speedup vs baseline: 1.1073x; 1.0729x over previous
#include <cuda_runtime.h>
#include <cuda_fp16.h>
#include <cstdint>

#define N_NODES 25000
#define N_PAD   25088          // 98 * 256
#define E_EDGES 400000
#define F_IN_   133
#define HC_     512
#define KP      144            // padded K (multiple of 16)
#define TPAD    152            // SMEM row stride in halves
#define BN_EPS_ 1e-5f
#define NEG_SLOPE_ 0.2f
#define W_SCALE 64.0f
#define W_INV   0.015625f
#define NROWT   98             // row tiles of 256 rows
#define NROWG   18             // persistent row groups
#define NCOLB   8              // column blocks

// ---------------- device scratch (static) -----------------------------------
__device__ __half g_xlh[(size_t)N_NODES * HC_];   // x@Wl in fp16
__device__ __half g_xrh[(size_t)N_NODES * HC_];   // x@Wr in fp16
__device__ __half g_xh [(size_t)N_PAD * KP];      // x in fp16
__device__ __half g_wh [(size_t)1024 * KP];       // W (scaled) in fp16
__device__ int    g_counts[N_NODES];
__device__ int    g_offsets[N_NODES + 1];
__device__ int    g_cursor[N_NODES];
__device__ int    g_csr_src[E_EDGES];
__device__ float2 g_gd[N_NODES];                  // {gout, dinv}

// ---------------- static streams/events -------------------------------------
static cudaStream_t g_s1;
static cudaEvent_t  g_eFork, g_eJoin, g_eW;
namespace {
struct StreamInit {
    StreamInit() {
        cudaStreamCreateWithFlags(&g_s1, cudaStreamNonBlocking);
        cudaEventCreateWithFlags(&g_eFork, cudaEventDisableTiming);
        cudaEventCreateWithFlags(&g_eJoin, cudaEventDisableTiming);
        cudaEventCreateWithFlags(&g_eW, cudaEventDisableTiming);
    }
} g_stream_init;
}

// ---------------- helpers ---------------------------------------------------
__device__ __forceinline__ uint32_t smem_to_u32(const void* p) {
    uint32_t a;
    asm("{ .reg .u64 t; cvta.to.shared.u64 t, %1; cvt.u32.u64 %0, t; }"
        : "=r"(a) : "l"(p));
    return a;
}
__device__ __forceinline__ void cp16(uint32_t dst, const void* src) {
    asm volatile("cp.async.cg.shared.global [%0], [%1], 16;" :: "r"(dst), "l"(src));
}

#define LDM_X4(r, addr) \
    asm volatile("ldmatrix.sync.aligned.m8n8.x4.shared.b16 {%0,%1,%2,%3}, [%4];" \
        : "=r"((r)[0]), "=r"((r)[1]), "=r"((r)[2]), "=r"((r)[3]) : "r"(addr))

__device__ __forceinline__ void mma16816(float* d, const uint32_t* a,
                                         uint32_t b0, uint32_t b1) {
    asm volatile("mma.sync.aligned.m16n8k16.row.col.f32.f16.f16.f32 "
        "{%0,%1,%2,%3}, {%4,%5,%6,%7}, {%8,%9}, {%0,%1,%2,%3};"
        : "+f"(d[0]), "+f"(d[1]), "+f"(d[2]), "+f"(d[3])
        : "r"(a[0]), "r"(a[1]), "r"(a[2]), "r"(a[3]), "r"(b0), "r"(b1));
}

// ---------------- conversions ------------------------------------------------
__global__ void conv_x_kernel(const float* __restrict__ x) {
    int i8 = blockIdx.x * blockDim.x + threadIdx.x;
    if (i8 >= N_PAD * KP / 8) return;
    int i = i8 * 8;
    int r = i / KP, k0 = i - r * KP;
    __half h[8];
    const float* xp = x + (size_t)r * F_IN_ + k0;
    #pragma unroll
    for (int j = 0; j < 8; j++) {
        int k = k0 + j;
        float v = (r < N_NODES && k < F_IN_) ? __ldg(xp + j) : 0.f;
        h[j] = __float2half_rn(v);
    }
    *(uint4*)(g_xh + i) = *(uint4*)h;
}

__global__ void conv_w_kernel(const float* __restrict__ Wl,
                              const float* __restrict__ Wr) {
    int i = blockIdx.x * blockDim.x + threadIdx.x;
    if (i >= 1024 * KP) return;
    int n = i / KP, k = i - n * KP;
    float v = 0.f;
    if (k < F_IN_)
        v = W_SCALE * ((n < HC_) ? Wl[(size_t)k * HC_ + n]
                                 : Wr[(size_t)k * HC_ + (n - HC_)]);
    g_wh[i] = __float2half_rn(v);
}

// ---------------- persistent fp16 mma GEMM, 512 thr, M=256 tiles -------------
#define A_TILE_H (256 * TPAD)
#define B_TILE_H (128 * TPAD)
#define SM_TOTAL ((2 * A_TILE_H + B_TILE_H) * 2)   // 194560 B

__global__ __launch_bounds__(512, 1) void gemm_mma_kernel() {
    extern __shared__ __half smem[];
    __half* A0 = smem;
    __half* A1 = A0 + A_TILE_H;
    __half* Bh = A1 + A_TILE_H;

    const int tid  = threadIdx.x;
    const int colb = blockIdx.x & 7;
    const int rowg = blockIdx.x >> 3;

    // pin B slab once (128 rows x 18 chunks)
    {
        const size_t brow0 = (size_t)colb * 128 * KP;
        for (int idx = tid; idx < 2304; idx += 512) {
            int row = idx / 18;
            int j   = idx - row * 18;
            *(uint4*)(Bh + row * TPAD + j * 8) =
                *(const uint4*)(g_wh + brow0 + (size_t)row * KP + j * 8);
        }
    }

    const uint32_t abase[2] = { smem_to_u32(A0), smem_to_u32(A1) };
    const uint32_t b_base = smem_to_u32(Bh);

    int c_row[9], c_col[9];
    #pragma unroll
    for (int j = 0; j < 9; j++) {
        int idx = tid + 512 * j;
        c_row[j] = idx / 18;
        c_col[j] = idx - c_row[j] * 18;
    }

    // prologue
    {
        const size_t arow0 = (size_t)rowg * 256 * KP;
        #pragma unroll
        for (int j = 0; j < 9; j++)
            cp16(abase[0] + (uint32_t)(c_row[j] * TPAD + c_col[j] * 8) * 2,
                 g_xh + arow0 + (size_t)c_row[j] * KP + c_col[j] * 8);
        asm volatile("cp.async.commit_group;");
    }

    const int wid = tid >> 5;
    const int lid = tid & 31;
    const int wm = (wid & 7) * 32;
    const int wn = (wid >> 3) * 64;

    const uint32_t a_off0 = ((uint32_t)(wm + (lid & 15)) * TPAD + (lid >> 4) * 8) * 2;
    const uint32_t b_row  = wn + (lid & 7) + ((lid >> 4) << 3);
    const uint32_t b_off0 = ((uint32_t)b_row * TPAD + ((lid >> 3) & 1) * 8) * 2;

    const int gc0 = colb * 128;
    __half* obase = (gc0 < HC_) ? g_xlh : g_xrh;
    const int ocol0 = (gc0 < HC_) ? gc0 : gc0 - HC_;

    int buf = 0;
    for (int rt = rowg; rt < NROWT; rt += NROWG) {
        const int nrt = rt + NROWG;
        if (nrt < NROWT) {
            const size_t arow0 = (size_t)nrt * 256 * KP;
            #pragma unroll
            for (int j = 0; j < 9; j++)
                cp16(abase[buf ^ 1] + (uint32_t)(c_row[j] * TPAD + c_col[j] * 8) * 2,
                     g_xh + arow0 + (size_t)c_row[j] * KP + c_col[j] * 8);
            asm volatile("cp.async.commit_group;");
            asm volatile("cp.async.wait_group 1;");
        } else {
            asm volatile("cp.async.wait_group 0;");
        }
        __syncthreads();

        const uint32_t a_base = abase[buf];

        float acc[2][8][4];
        #pragma unroll
        for (int mt = 0; mt < 2; mt++)
            #pragma unroll
            for (int nt = 0; nt < 8; nt++)
                #pragma unroll
                for (int j = 0; j < 4; j++) acc[mt][nt][j] = 0.f;

        #pragma unroll
        for (int ks = 0; ks < 9; ks++) {
            const uint32_t kb = ks * 32;
            uint32_t a_hi[2][4];
            #pragma unroll
            for (int mt = 0; mt < 2; mt++)
                LDM_X4(a_hi[mt], a_base + a_off0 + mt * (16 * TPAD * 2) + kb);
            uint32_t b_hi[4][4];
            #pragma unroll
            for (int np = 0; np < 4; np++)
                LDM_X4(b_hi[np], b_base + b_off0 + np * (16 * TPAD * 2) + kb);
            #pragma unroll
            for (int mt = 0; mt < 2; mt++) {
                #pragma unroll
                for (int nt = 0; nt < 8; nt++) {
                    const uint32_t* bh = &b_hi[nt >> 1][(nt & 1) * 2];
                    mma16816(acc[mt][nt], a_hi[mt], bh[0], bh[1]);
                }
            }
        }

        #pragma unroll
        for (int mt = 0; mt < 2; mt++) {
            int r0 = rt * 256 + wm + mt * 16 + (lid >> 2);
            #pragma unroll
            for (int nt = 0; nt < 8; nt++) {
                int col = ocol0 + wn + nt * 8 + (lid & 3) * 2;
                float v0 = acc[mt][nt][0] * W_INV, v1 = acc[mt][nt][1] * W_INV;
                float v2 = acc[mt][nt][2] * W_INV, v3 = acc[mt][nt][3] * W_INV;
                if (r0 < N_NODES)
                    *(__half2*)(obase + (size_t)r0 * HC_ + col) = __floats2half2_rn(v0, v1);
                if (r0 + 8 < N_NODES)
                    *(__half2*)(obase + (size_t)(r0 + 8) * HC_ + col) = __floats2half2_rn(v2, v3);
            }
        }
        __syncthreads();
        buf ^= 1;
    }
}

// ---------------- CSR build -------------------------------------------------
__global__ void hist_kernel(const int* __restrict__ ei) {
    int e = blockIdx.x * blockDim.x + threadIdx.x;
    if (e < E_EDGES) atomicAdd(&g_counts[ei[E_EDGES + e]], 1);
}

__global__ __launch_bounds__(1024) void scan_kernel() {
    __shared__ int warp_sums[32];
    __shared__ int s_carry;
    const int t = threadIdx.x;
    const int lane = t & 31;
    const int w = t >> 5;
    if (t == 0) { s_carry = 0; g_offsets[0] = 0; }
    __syncthreads();
    for (int base = 0; base < N_NODES; base += 1024) {
        int i = base + t;
        int v = (i < N_NODES) ? g_counts[i] : 0;
        int s = v;
        #pragma unroll
        for (int d = 1; d < 32; d <<= 1) {
            int n = __shfl_up_sync(0xffffffffu, s, d);
            if (lane >= d) s += n;
        }
        if (lane == 31) warp_sums[w] = s;
        __syncthreads();
        if (w == 0) {
            int ws = warp_sums[lane];
            #pragma unroll
            for (int d = 1; d < 32; d <<= 1) {
                int n = __shfl_up_sync(0xffffffffu, ws, d);
                if (lane >= d) ws += n;
            }
            warp_sums[lane] = ws;
        }
        __syncthreads();
        int incl = s + (w > 0 ? warp_sums[w - 1] : 0);
        int carry = s_carry;
        if (i < N_NODES) {
            g_offsets[i + 1] = carry + incl;
            g_cursor[i] = carry + incl - v;
        }
        __syncthreads();
        if (t == 1023) s_carry = carry + incl;
        __syncthreads();
    }
}

__global__ void scatter_kernel(const int* __restrict__ ei) {
    int e = blockIdx.x * blockDim.x + threadIdx.x;
    if (e < E_EDGES) {
        int d = ei[E_EDGES + e];
        int p = atomicAdd(&g_cursor[d], 1);
        g_csr_src[p] = ei[e];
    }
}

// ---------------- GATv2 aggregation: 2 warps/node, half2 score path ----------
__global__ __launch_bounds__(256) void agg_kernel(
    const float* __restrict__ att,  const float* __restrict__ b1,
    const float* __restrict__ bn_g, const float* __restrict__ bn_b,
    const float* __restrict__ bn_m, const float* __restrict__ bn_v,
    const float* __restrict__ prelu_w, const float* __restrict__ Wg)
{
    const int gw   = threadIdx.x >> 5;            // warp in block (0..7)
    const int node = blockIdx.x * 4 + (gw >> 1);
    const int half = gw & 1;
    const int lane = threadIdx.x & 31;
    __shared__ float red[8];

    bool active = (node < N_NODES);
    int rs = 0, cnt = 1;
    __half2 xr2[4], at2[4];
    float acc[8];
    float den = 0.f;

    const int c0 = half * 256 + lane * 8;
    const uint4* __restrict__ xlrow = (const uint4*)g_xlh;   // 64 uint4 per row
    const uint4* __restrict__ xrrow = (const uint4*)g_xrh;
    const size_t uidx = (size_t)node * 64 + half * 32 + lane;
    const __half2 k02 = __floats2half2_rn(NEG_SLOPE_, NEG_SLOPE_);

    if (active) {
        {
            uint4 xv = __ldg(&xrrow[uidx]);
            xr2[0] = *(__half2*)&xv.x; xr2[1] = *(__half2*)&xv.y;
            xr2[2] = *(__half2*)&xv.z; xr2[3] = *(__half2*)&xv.w;
        }
        {
            const float4* q = (const float4*)(att + c0);
            #pragma unroll
            for (int i = 0; i < 2; i++) {
                float4 a = __ldg(q + i);
                at2[2*i]   = __floats2half2_rn(a.x, a.y);
                at2[2*i+1] = __floats2half2_rn(a.z, a.w);
            }
        }
        rs = g_offsets[node];
        cnt = g_offsets[node + 1] - rs + 1;
        #pragma unroll
        for (int i = 0; i < 8; i++) acc[i] = 0.f;

        uint4 u = __ldg(&xlrow[uidx]);      // self loop first
        for (int k = 0; k < cnt; k++) {
            uint4 n = u;
            if (k + 1 < cnt) {
                int ns = g_csr_src[rs + k];
                n = __ldg(&xlrow[(size_t)ns * 64 + half * 32 + lane]);
            }
            const __half2* u2 = (const __half2*)&u;
            // score path in half2: lrelu(s) = max(s, 0.2*s)
            __half2 p2h = __floats2half2_rn(0.f, 0.f);
            #pragma unroll
            for (int i = 0; i < 4; i++) {
                __half2 s2 = __hadd2(u2[i], xr2[i]);
                __half2 l2 = __hmax2(s2, __hmul2(s2, k02));
                p2h = __hfma2(at2[i], l2, p2h);
            }
            float2 pf = __half22float2(p2h);
            float p2 = pf.x + pf.y;
            p2 += __shfl_xor_sync(0xffffffffu, p2, 1);
            p2 += __shfl_xor_sync(0xffffffffu, p2, 2);
            p2 += __shfl_xor_sync(0xffffffffu, p2, 4);  // per-head score (8 lanes)
            float w = __expf(p2);
            den += w;
            // feature path in fp32
            #pragma unroll
            for (int i = 0; i < 4; i++) {
                float2 t = __half22float2(u2[i]);
                acc[2*i]   += w * t.x;
                acc[2*i+1] += w * t.y;
            }
            u = n;
        }
    }

    float part = 0.f;
    if (active) {
        const float inv = 1.f / den;
        const float pw = prelu_w[0];
        #pragma unroll
        for (int i = 0; i < 2; i++) {
            float4 bb = __ldg((const float4*)(b1   + c0) + i);
            float4 gm = __ldg((const float4*)(bn_g + c0) + i);
            float4 bt = __ldg((const float4*)(bn_b + c0) + i);
            float4 mv = __ldg((const float4*)(bn_m + c0) + i);
            float4 vv = __ldg((const float4*)(bn_v + c0) + i);
            float4 wg = __ldg((const float4*)(Wg   + c0) + i);
            float h;
            h = acc[4*i+0] * inv + bb.x;
            h = (h - mv.x) * rsqrtf(vv.x + BN_EPS_) * gm.x + bt.x;
            h = h >= 0.f ? h : pw * h;  part += h * wg.x;
            h = acc[4*i+1] * inv + bb.y;
            h = (h - mv.y) * rsqrtf(vv.y + BN_EPS_) * gm.y + bt.y;
            h = h >= 0.f ? h : pw * h;  part += h * wg.y;
            h = acc[4*i+2] * inv + bb.z;
            h = (h - mv.z) * rsqrtf(vv.z + BN_EPS_) * gm.z + bt.z;
            h = h >= 0.f ? h : pw * h;  part += h * wg.z;
            h = acc[4*i+3] * inv + bb.w;
            h = (h - mv.w) * rsqrtf(vv.w + BN_EPS_) * gm.w + bt.w;
            h = h >= 0.f ? h : pw * h;  part += h * wg.w;
        }
        #pragma unroll
        for (int o = 16; o; o >>= 1) part += __shfl_xor_sync(0xffffffffu, part, o);
    }
    if (lane == 0) red[gw] = part;
    __syncthreads();
    if (active && half == 0 && lane == 0)
        g_gd[node] = make_float2(red[gw] + red[gw + 1], rsqrtf((float)cnt));
}

// ---------------- GCNConv (OUT=1): 8 lanes per node --------------------------
__global__ void gcn_kernel(const float* __restrict__ bg, float* __restrict__ out) {
    int gthread = blockIdx.x * blockDim.x + threadIdx.x;
    int node = gthread >> 3;
    int sl   = gthread & 7;
    if (node >= N_NODES) return;
    int rs = g_offsets[node], re = g_offsets[node + 1];
    float2 self = g_gd[node];
    float di = self.y;
    float s = (sl == 0) ? di * self.x : 0.f;
    for (int j = rs + sl; j < re; j += 8) {
        float2 gd = __ldg(&g_gd[g_csr_src[j]]);
        s += gd.y * gd.x;
    }
    s += __shfl_xor_sync(0xffffffffu, s, 1);
    s += __shfl_xor_sync(0xffffffffu, s, 2);
    s += __shfl_xor_sync(0xffffffffu, s, 4);
    if (sl == 0) out[node] = bg[0] + di * s;
}

// ---------------- launch ----------------------------------------------------
extern "C" void kernel_launch(void* const* d_in, const int* in_sizes, int n_in,
                              void* d_out, int out_size)
{
    const float* x    = (const float*)d_in[0];
    const int*   ei   = (const int*)  d_in[1];
    const float* Wl   = (const float*)d_in[2];
    const float* Wr   = (const float*)d_in[3];
    const float* att  = (const float*)d_in[4];
    const float* b1   = (const float*)d_in[5];
    const float* bn_g = (const float*)d_in[6];
    const float* bn_b = (const float*)d_in[7];
    const float* bn_m = (const float*)d_in[8];
    const float* bn_v = (const float*)d_in[9];
    const float* pw   = (const float*)d_in[10];
    const float* Wg   = (const float*)d_in[11];
    const float* bg   = (const float*)d_in[12];
    float* out = (float*)d_out;

    cudaFuncSetAttribute(gemm_mma_kernel,
                         cudaFuncAttributeMaxDynamicSharedMemorySize, SM_TOTAL);

    void* countsPtr = nullptr;
    cudaGetSymbolAddress(&countsPtr, g_counts);

    // Fork: conv_w then CSR chain on side stream.
    cudaEventRecord(g_eFork, 0);
    cudaStreamWaitEvent(g_s1, g_eFork, 0);
    conv_w_kernel<<<(1024 * KP + 255) / 256, 256, 0, g_s1>>>(Wl, Wr);
    cudaEventRecord(g_eW, g_s1);
    cudaMemsetAsync(countsPtr, 0, N_NODES * sizeof(int), g_s1);
    hist_kernel<<<(E_EDGES + 255) / 256, 256, 0, g_s1>>>(ei);
    scan_kernel<<<1, 1024, 0, g_s1>>>();
    scatter_kernel<<<(E_EDGES + 255) / 256, 256, 0, g_s1>>>(ei);
    cudaEventRecord(g_eJoin, g_s1);

    // Main stream: conv_x, wait for conv_w, then persistent GEMM.
    conv_x_kernel<<<(N_PAD * KP / 8 + 255) / 256, 256>>>(x);
    cudaStreamWaitEvent(0, g_eW, 0);
    gemm_mma_kernel<<<NROWG * NCOLB, 512, SM_TOTAL>>>();

    // Join, then aggregation + GCN.
    cudaStreamWaitEvent(0, g_eJoin, 0);
    agg_kernel<<<(N_NODES + 3) / 4, 256>>>(att, b1, bn_g, bn_b, bn_m, bn_v, pw, Wg);
    gcn_kernel<<<(N_NODES * 8 + 255) / 256, 256>>>(bg, out);
}